// round 5
// baseline (speedup 1.0000x reference)
#include <cuda_runtime.h>
#include <cuda_bf16.h>
#include <cstdint>

// Problem constants (fixed by the dataset)
static constexpr int NN    = 100000;   // nodes
static constexpr int EE    = 3200000;  // edges
static constexpr int DIN   = 128;
static constexpr int HID   = 16;
static constexpr int DOUT  = 12;
static constexpr int NMID  = 11;

static constexpr int SCAN_B = 1024;
static constexpr int NBLK   = (NN + SCAN_B - 1) / SCAN_B;   // 98

// ---------------- scratch (device globals; no allocation allowed) -----------
// NOTE: these are referenced ONLY inside device code. Passing a __device__
// symbol as a host-side kernel argument yields the host shadow address (UB) —
// that was the rel_err=1.0 bug in the previous round.
__device__ int   g_is64;
__device__ float g_deg[NN];
__device__ float g_dis[NN];      // rsqrt(deg)
__device__ float g_selfw[NN];    // 1/deg
__device__ int   g_cnt[NN];      // histogram, then fill counters
__device__ int   g_ptr[NN + 1];  // CSR row (by dst) pointers
__device__ int   g_bsum[128];
__device__ int   g_src[EE];      // CSR-sorted source node
__device__ float g_norm[EE];     // CSR-sorted edge norm
__device__ float g_buf0[NN * HID];   // h (layer input)
__device__ float g_buf1[NN * HID];   // tmp = h @ W

// ---------------- helpers ---------------------------------------------------
__device__ __forceinline__ int eidx(const void* ei, bool is64, long long i) {
    if (is64) return (int)((const long long*)ei)[i];
    return ((const int*)ei)[i];
}

// Detect int64 vs int32 edge_index: if int64 (values < 2^31), every odd
// 32-bit word is a zero high-word. With int32 data, odd words are random
// node ids in [0,100000); 1024 samples all-zero is impossible in practice.
__global__ void k_detect(const unsigned int* p) {
    __shared__ unsigned int s_or;
    if (threadIdx.x == 0) s_or = 0u;
    __syncthreads();
    unsigned int acc = 0;
    for (int i = threadIdx.x; i < 1024; i += blockDim.x)
        acc |= p[2 * i + 1];
    if (acc) atomicOr(&s_or, acc);
    __syncthreads();
    if (threadIdx.x == 0) g_is64 = (s_or == 0u) ? 1 : 0;
}

__global__ void k_zero() {
    int i = blockIdx.x * blockDim.x + threadIdx.x;
    if (i < NN) { g_deg[i] = 0.f; g_cnt[i] = 0; }
}

// deg[c] += w[e]; cnt[c]++  (histogram pass)
__global__ void k_degcnt(const void* ei, const float* __restrict__ w) {
    bool is64 = (g_is64 != 0);
    for (int e = blockIdx.x * blockDim.x + threadIdx.x; e < EE;
         e += gridDim.x * blockDim.x) {
        int c = eidx(ei, is64, (long long)EE + e);
        atomicAdd(&g_deg[c], w[e]);
        atomicAdd(&g_cnt[c], 1);
    }
}

__global__ void k_norminv() {
    int i = blockIdx.x * blockDim.x + threadIdx.x;
    if (i < NN) {
        float d = g_deg[i] + 1.0f;
        g_dis[i]   = rsqrtf(d);
        g_selfw[i] = 1.0f / d;
    }
}

// Exclusive scan of g_cnt -> g_ptr (3-kernel two-level scan)
__global__ void k_scan1() {
    __shared__ int s[SCAN_B];
    int i = blockIdx.x * SCAN_B + threadIdx.x;
    int v = (i < NN) ? g_cnt[i] : 0;
    s[threadIdx.x] = v;
    __syncthreads();
    for (int off = 1; off < SCAN_B; off <<= 1) {
        int t = (threadIdx.x >= off) ? s[threadIdx.x - off] : 0;
        __syncthreads();
        s[threadIdx.x] += t;
        __syncthreads();
    }
    if (i < NN) g_ptr[i] = s[threadIdx.x] - v;   // exclusive
    if (threadIdx.x == SCAN_B - 1) g_bsum[blockIdx.x] = s[SCAN_B - 1];
}

__global__ void k_scan2() {
    if (threadIdx.x == 0) {
        int acc = 0;
        for (int b = 0; b < NBLK; b++) { int t = g_bsum[b]; g_bsum[b] = acc; acc += t; }
    }
}

__global__ void k_scan3() {
    int i = blockIdx.x * blockDim.x + threadIdx.x;
    if (i < NN) {
        g_ptr[i] += g_bsum[i / SCAN_B];
        g_cnt[i] = 0;                 // reuse as fill counters
    }
    if (i == 0) g_ptr[NN] = EE;
}

// Scatter edges into CSR order (by destination), computing norm on the fly
__global__ void k_scatter(const void* ei, const float* __restrict__ w) {
    bool is64 = (g_is64 != 0);
    for (int e = blockIdx.x * blockDim.x + threadIdx.x; e < EE;
         e += gridDim.x * blockDim.x) {
        int r = eidx(ei, is64, e);
        int c = eidx(ei, is64, (long long)EE + e);
        int pos = g_ptr[c] + atomicAdd(&g_cnt[c], 1);
        g_src[pos]  = r;
        g_norm[pos] = g_dis[r] * w[e] * g_dis[c];
    }
}

// ---------------- dense phases ----------------------------------------------
// Layer 0 GEMM: x[N,128] @ W0[128,16] -> g_buf1. 16 nodes x 16 feats / block.
__global__ void k_gemm0(const float* __restrict__ x, const float* __restrict__ W0) {
    __shared__ float Ws[DIN * HID];   // 8 KB
    __shared__ float xs[16 * DIN];    // 8 KB
    int tid = threadIdx.x;
    for (int i = tid; i < DIN * HID; i += 256) Ws[i] = W0[i];
    int n0 = blockIdx.x * 16;
    for (int i = tid; i < 16 * DIN; i += 256) {
        int nn = n0 + i / DIN;
        xs[i] = (nn < NN) ? x[(size_t)nn * DIN + (i % DIN)] : 0.f;
    }
    __syncthreads();
    int ln = tid >> 4, f = tid & 15;
    int n = n0 + ln;
    if (n < NN) {
        float acc = 0.f;
        #pragma unroll
        for (int k = 0; k < DIN; k++) acc += xs[ln * DIN + k] * Ws[k * HID + f];
        g_buf1[(size_t)n * HID + f] = acc;
    }
}

// Small GEMM: g_buf1[n,f] = sum_k g_buf0[n,k] * W[k,FOUT]
template <int FOUT>
__global__ void k_gemmN(const float* __restrict__ W) {
    int t = blockIdx.x * blockDim.x + threadIdx.x;
    if (t >= NN * FOUT) return;
    int n = t / FOUT, f = t - n * FOUT;
    const float* hr = g_buf0 + (size_t)n * HID;
    float acc = 0.f;
    #pragma unroll
    for (int k = 0; k < HID; k++) acc += hr[k] * W[k * FOUT + f];
    g_buf1[t] = acc;
}

// ---------------- sparse aggregation ----------------------------------------
// dst[n,f] = relu( selfw[n]*tmp[n,f] + sum_{e in CSR(n)} norm[e]*tmp[src[e],f] + b[f] )
// tmp = g_buf1 (always). dst = g_buf0 (TO_OUT=false) or the harness out buffer.
// 16 threads per node; feature lanes f >= F are idle (F=12 on the last layer).
template <int F, bool TO_OUT>
__global__ void k_agg(const float* __restrict__ bias, float* __restrict__ outp) {
    int gt = blockIdx.x * blockDim.x + threadIdx.x;
    int n  = gt >> 4;
    int f  = gt & 15;
    if (n >= NN) return;
    const float* __restrict__ tmp = g_buf1;
    bool act = (f < F);
    float acc = act ? g_selfw[n] * tmp[(size_t)n * F + f] : 0.f;
    int e   = g_ptr[n];
    int end = g_ptr[n + 1];
    for (; e + 1 < end; e += 2) {
        int   s0 = g_src[e],  s1 = g_src[e + 1];
        float w0 = g_norm[e], w1 = g_norm[e + 1];
        if (act) {
            acc += w0 * tmp[(size_t)s0 * F + f];
            acc += w1 * tmp[(size_t)s1 * F + f];
        }
    }
    if (e < end) {
        int s = g_src[e];
        if (act) acc += g_norm[e] * tmp[(size_t)s * F + f];
    }
    if (act) {
        float r = fmaxf(acc + bias[f], 0.f);
        if (TO_OUT) outp[(size_t)n * F + f] = r;
        else        g_buf0[(size_t)n * F + f] = r;
    }
}

// ---------------- launch ----------------------------------------------------
extern "C" void kernel_launch(void* const* d_in, const int* in_sizes, int n_in,
                              void* d_out, int out_size) {
    const float* x     = (const float*)d_in[0];
    const void*  ei    = d_in[1];                 // int32 or int64, autodetected
    const float* w     = (const float*)d_in[2];
    const float* W0    = (const float*)d_in[3];
    const float* b0    = (const float*)d_in[4];
    const float* Wmid  = (const float*)d_in[5];
    const float* bmid  = (const float*)d_in[6];
    const float* Wlast = (const float*)d_in[7];
    const float* blast = (const float*)d_in[8];
    float* out = (float*)d_out;

    const int TB = 256;
    const int nblkN  = (NN + TB - 1) / TB;
    const int nblkE  = 2048;                       // grid-stride over E
    const int nblkNG = (NN * 16 + TB - 1) / TB;    // 16 threads/node

    // --- preprocessing (per launch; graph-captured) ---
    k_detect<<<1, 256>>>((const unsigned int*)ei);
    k_zero<<<nblkN, TB>>>();
    k_degcnt<<<nblkE, TB>>>(ei, w);
    k_norminv<<<nblkN, TB>>>();
    k_scan1<<<NBLK, SCAN_B>>>();
    k_scan2<<<1, 32>>>();
    k_scan3<<<nblkN, TB>>>();
    k_scatter<<<nblkE, TB>>>(ei, w);

    // --- layer 0: x @ W0 -> buf1; aggregate -> buf0 ---
    k_gemm0<<<(NN + 15) / 16, 256>>>(x, W0);
    k_agg<HID, false><<<nblkNG, TB>>>(b0, nullptr);

    // --- 11 middle layers ---
    for (int l = 0; l < NMID; l++) {
        k_gemmN<HID><<<(NN * HID + TB - 1) / TB, TB>>>(Wmid + (size_t)l * HID * HID);
        k_agg<HID, false><<<nblkNG, TB>>>(bmid + (size_t)l * HID, nullptr);
    }

    // --- last layer: 16 -> 12, aggregate straight into d_out ---
    k_gemmN<DOUT><<<(NN * DOUT + TB - 1) / TB, TB>>>(Wlast);
    k_agg<DOUT, true><<<nblkNG, TB>>>(blast, out);
}

// round 6
// speedup vs baseline: 1.3249x; 1.3249x over previous
#include <cuda_runtime.h>
#include <cuda_bf16.h>
#include <cstdint>

// Problem constants (fixed by the dataset)
static constexpr int NN    = 100000;   // nodes
static constexpr int EE    = 3200000;  // edges
static constexpr int DIN   = 128;
static constexpr int HID   = 16;
static constexpr int DOUT  = 12;
static constexpr int NMID  = 11;

static constexpr int SCAN_B = 1024;
static constexpr int NBLK   = (NN + SCAN_B - 1) / SCAN_B;   // 98

// ---------------- scratch (device globals; referenced only in device code) --
__device__ int    g_is64;
__device__ float  g_deg[NN];
__device__ float  g_dis[NN];       // rsqrt(deg)
__device__ float  g_selfw[NN];     // 1/deg
__device__ int    g_cnt[NN];       // histogram, then fill counters
__device__ int    g_ptr[NN + 1];   // CSR row (by dst) pointers
__device__ int    g_bsum[128];
__device__ float2 g_edge[EE];      // packed {src_as_float_bits, norm}
__device__ float  g_buf0[NN * HID];
__device__ float  g_buf1[NN * HID];

// ---------------- helpers ---------------------------------------------------
__device__ __forceinline__ int eidx(const void* ei, bool is64, long long i) {
    if (is64) return (int)((const long long*)ei)[i];
    return ((const int*)ei)[i];
}

// Detect int64 vs int32 edge_index (int64 values < 2^31 -> odd words all zero)
__global__ void k_detect(const unsigned int* p) {
    __shared__ unsigned int s_or;
    if (threadIdx.x == 0) s_or = 0u;
    __syncthreads();
    unsigned int acc = 0;
    for (int i = threadIdx.x; i < 1024; i += blockDim.x)
        acc |= p[2 * i + 1];
    if (acc) atomicOr(&s_or, acc);
    __syncthreads();
    if (threadIdx.x == 0) g_is64 = (s_or == 0u) ? 1 : 0;
}

__global__ void k_zero() {
    int i = blockIdx.x * blockDim.x + threadIdx.x;
    if (i < NN) { g_deg[i] = 0.f; g_cnt[i] = 0; }
}

__global__ void k_degcnt(const void* ei, const float* __restrict__ w) {
    bool is64 = (g_is64 != 0);
    for (int e = blockIdx.x * blockDim.x + threadIdx.x; e < EE;
         e += gridDim.x * blockDim.x) {
        int c = eidx(ei, is64, (long long)EE + e);
        atomicAdd(&g_deg[c], w[e]);
        atomicAdd(&g_cnt[c], 1);
    }
}

__global__ void k_norminv() {
    int i = blockIdx.x * blockDim.x + threadIdx.x;
    if (i < NN) {
        float d = g_deg[i] + 1.0f;
        g_dis[i]   = rsqrtf(d);
        g_selfw[i] = 1.0f / d;
    }
}

__global__ void k_scan1() {
    __shared__ int s[SCAN_B];
    int i = blockIdx.x * SCAN_B + threadIdx.x;
    int v = (i < NN) ? g_cnt[i] : 0;
    s[threadIdx.x] = v;
    __syncthreads();
    for (int off = 1; off < SCAN_B; off <<= 1) {
        int t = (threadIdx.x >= off) ? s[threadIdx.x - off] : 0;
        __syncthreads();
        s[threadIdx.x] += t;
        __syncthreads();
    }
    if (i < NN) g_ptr[i] = s[threadIdx.x] - v;   // exclusive
    if (threadIdx.x == SCAN_B - 1) g_bsum[blockIdx.x] = s[SCAN_B - 1];
}

__global__ void k_scan2() {
    if (threadIdx.x == 0) {
        int acc = 0;
        for (int b = 0; b < NBLK; b++) { int t = g_bsum[b]; g_bsum[b] = acc; acc += t; }
    }
}

__global__ void k_scan3() {
    int i = blockIdx.x * blockDim.x + threadIdx.x;
    if (i < NN) {
        g_ptr[i] += g_bsum[i / SCAN_B];
        g_cnt[i] = 0;                 // reuse as fill counters
    }
    if (i == 0) g_ptr[NN] = EE;
}

// Scatter edges into CSR order (by destination) as packed {src, norm} (8B)
__global__ void k_scatter(const void* ei, const float* __restrict__ w) {
    bool is64 = (g_is64 != 0);
    for (int e = blockIdx.x * blockDim.x + threadIdx.x; e < EE;
         e += gridDim.x * blockDim.x) {
        int r = eidx(ei, is64, e);
        int c = eidx(ei, is64, (long long)EE + e);
        int pos = g_ptr[c] + atomicAdd(&g_cnt[c], 1);
        g_edge[pos] = make_float2(__int_as_float(r), g_dis[r] * w[e] * g_dis[c]);
    }
}

// ---------------- layer 0 GEMM: x[N,128] @ W0[128,16] -> g_buf0 -------------
__global__ void k_gemm0(const float* __restrict__ x, const float* __restrict__ W0) {
    __shared__ float Ws[DIN * HID];   // 8 KB
    __shared__ float xs[16 * DIN];    // 8 KB
    int tid = threadIdx.x;
    for (int i = tid; i < DIN * HID; i += 256) Ws[i] = W0[i];
    int n0 = blockIdx.x * 16;
    for (int i = tid; i < 16 * DIN; i += 256) {
        int nn = n0 + i / DIN;
        xs[i] = (nn < NN) ? x[(size_t)nn * DIN + (i % DIN)] : 0.f;
    }
    __syncthreads();
    int ln = tid >> 4, f = tid & 15;
    int n = n0 + ln;
    if (n < NN) {
        float acc = 0.f;
        #pragma unroll
        for (int k = 0; k < DIN; k++) acc += xs[ln * DIN + k] * Ws[k * HID + f];
        g_buf0[(size_t)n * HID + f] = acc;
    }
}

// ---------------- fused agg(+bias+relu) + next-layer GEMM -------------------
// 4 lanes per node; each lane owns 4 feats (float4).
//   h[n] = relu( selfw[n]*tmp[n] + sum_e norm*tmp[src] + b )
//   dst[n] = h[n] @ Wn      (Wn is [16,FOUT], FOUT<=16; pad cols with 0)
// rb selects read buffer (0: buf0, 1: buf1); write goes to the other.
template <int FOUT>
__global__ void __launch_bounds__(256) k_fused(const float* __restrict__ bias,
                                               const float* __restrict__ Wn, int rb) {
    __shared__ float Ws[HID * 16];
    int tid = threadIdx.x;
    for (int i = tid; i < HID * 16; i += 256) {
        int k = i >> 4, fo = i & 15;
        Ws[i] = (fo < FOUT) ? Wn[k * FOUT + fo] : 0.f;
    }
    __syncthreads();

    int gt = blockIdx.x * blockDim.x + tid;
    int n  = gt >> 2;
    if (n >= NN) n = NN - 1;           // clamp: duplicate groups redo node NN-1
    int l4 = tid & 3;

    const float4* __restrict__ tmp = rb ? (const float4*)g_buf1 : (const float4*)g_buf0;
    float4*       __restrict__ dst = rb ? (float4*)g_buf0       : (float4*)g_buf1;

    float4 t  = tmp[n * 4 + l4];
    float  sw = g_selfw[n];
    float4 acc = make_float4(sw * t.x, sw * t.y, sw * t.z, sw * t.w);

    int e = g_ptr[n], end = g_ptr[n + 1];
    for (; e + 4 <= end; e += 4) {
        float2 e0 = g_edge[e],     e1 = g_edge[e + 1];
        float2 e2 = g_edge[e + 2], e3 = g_edge[e + 3];
        float4 v0 = tmp[__float_as_int(e0.x) * 4 + l4];
        float4 v1 = tmp[__float_as_int(e1.x) * 4 + l4];
        float4 v2 = tmp[__float_as_int(e2.x) * 4 + l4];
        float4 v3 = tmp[__float_as_int(e3.x) * 4 + l4];
        acc.x += e0.y * v0.x; acc.y += e0.y * v0.y; acc.z += e0.y * v0.z; acc.w += e0.y * v0.w;
        acc.x += e1.y * v1.x; acc.y += e1.y * v1.y; acc.z += e1.y * v1.z; acc.w += e1.y * v1.w;
        acc.x += e2.y * v2.x; acc.y += e2.y * v2.y; acc.z += e2.y * v2.z; acc.w += e2.y * v2.w;
        acc.x += e3.y * v3.x; acc.y += e3.y * v3.y; acc.z += e3.y * v3.z; acc.w += e3.y * v3.w;
    }
    for (; e < end; e++) {
        float2 ed = g_edge[e];
        float4 v  = tmp[__float_as_int(ed.x) * 4 + l4];
        acc.x += ed.y * v.x; acc.y += ed.y * v.y; acc.z += ed.y * v.z; acc.w += ed.y * v.w;
    }

    float4 b = ((const float4*)bias)[l4];      // agg layer feat dim is 16 here
    float4 h;
    h.x = fmaxf(acc.x + b.x, 0.f);
    h.y = fmaxf(acc.y + b.y, 0.f);
    h.z = fmaxf(acc.z + b.z, 0.f);
    h.w = fmaxf(acc.w + b.w, 0.f);

    // gather the full 16-feat row within the 4-lane group
    float hrow[16];
    int base = (tid & 31) & ~3;
    #pragma unroll
    for (int q = 0; q < 4; q++) {
        hrow[4 * q + 0] = __shfl_sync(0xffffffffu, h.x, base + q);
        hrow[4 * q + 1] = __shfl_sync(0xffffffffu, h.y, base + q);
        hrow[4 * q + 2] = __shfl_sync(0xffffffffu, h.z, base + q);
        hrow[4 * q + 3] = __shfl_sync(0xffffffffu, h.w, base + q);
    }

    float4 o = make_float4(0.f, 0.f, 0.f, 0.f);
    #pragma unroll
    for (int k = 0; k < HID; k++) {
        float hk = hrow[k];
        const float* wr = &Ws[k * 16 + l4 * 4];
        o.x += hk * wr[0]; o.y += hk * wr[1]; o.z += hk * wr[2]; o.w += hk * wr[3];
    }
    dst[n * 4 + l4] = o;     // duplicate clamped groups write identical values
}

// ---------------- final aggregation (F=12) into harness out -----------------
// tmp rows are stride-16 (cols 12..15 are zero-padded by k_fused<12>).
__global__ void __launch_bounds__(256) k_agg_last(const float* __restrict__ bias,
                                                  float* __restrict__ outp) {
    int gt = blockIdx.x * blockDim.x + threadIdx.x;
    int n  = gt >> 2;
    if (n >= NN) n = NN - 1;
    int l4 = threadIdx.x & 3;

    const float4* __restrict__ tmp = (const float4*)g_buf0;   // 12 fused layers end in buf0

    float4 t  = tmp[n * 4 + l4];
    float  sw = g_selfw[n];
    float4 acc = make_float4(sw * t.x, sw * t.y, sw * t.z, sw * t.w);

    int e = g_ptr[n], end = g_ptr[n + 1];
    for (; e + 4 <= end; e += 4) {
        float2 e0 = g_edge[e],     e1 = g_edge[e + 1];
        float2 e2 = g_edge[e + 2], e3 = g_edge[e + 3];
        float4 v0 = tmp[__float_as_int(e0.x) * 4 + l4];
        float4 v1 = tmp[__float_as_int(e1.x) * 4 + l4];
        float4 v2 = tmp[__float_as_int(e2.x) * 4 + l4];
        float4 v3 = tmp[__float_as_int(e3.x) * 4 + l4];
        acc.x += e0.y * v0.x; acc.y += e0.y * v0.y; acc.z += e0.y * v0.z; acc.w += e0.y * v0.w;
        acc.x += e1.y * v1.x; acc.y += e1.y * v1.y; acc.z += e1.y * v1.z; acc.w += e1.y * v1.w;
        acc.x += e2.y * v2.x; acc.y += e2.y * v2.y; acc.z += e2.y * v2.z; acc.w += e2.y * v2.w;
        acc.x += e3.y * v3.x; acc.y += e3.y * v3.y; acc.z += e3.y * v3.z; acc.w += e3.y * v3.w;
    }
    for (; e < end; e++) {
        float2 ed = g_edge[e];
        float4 v  = tmp[__float_as_int(ed.x) * 4 + l4];
        acc.x += ed.y * v.x; acc.y += ed.y * v.y; acc.z += ed.y * v.z; acc.w += ed.y * v.w;
    }

    if (l4 < 3) {   // only feats 0..11 exist
        float4 b = *(const float4*)(bias + 4 * l4);
        float4 r;
        r.x = fmaxf(acc.x + b.x, 0.f);
        r.y = fmaxf(acc.y + b.y, 0.f);
        r.z = fmaxf(acc.z + b.z, 0.f);
        r.w = fmaxf(acc.w + b.w, 0.f);
        *(float4*)(outp + (size_t)n * DOUT + 4 * l4) = r;   // 16B-aligned
    }
}

// ---------------- launch ----------------------------------------------------
extern "C" void kernel_launch(void* const* d_in, const int* in_sizes, int n_in,
                              void* d_out, int out_size) {
    const float* x     = (const float*)d_in[0];
    const void*  ei    = d_in[1];
    const float* w     = (const float*)d_in[2];
    const float* W0    = (const float*)d_in[3];
    const float* b0    = (const float*)d_in[4];
    const float* Wmid  = (const float*)d_in[5];
    const float* bmid  = (const float*)d_in[6];
    const float* Wlast = (const float*)d_in[7];
    const float* blast = (const float*)d_in[8];
    float* out = (float*)d_out;

    const int TB = 256;
    const int nblkN  = (NN + TB - 1) / TB;
    const int nblkE  = 2048;
    const int nblk4  = (NN * 4 + TB - 1) / TB;   // 4 lanes/node

    // --- preprocessing ---
    k_detect<<<1, 256>>>((const unsigned int*)ei);
    k_zero<<<nblkN, TB>>>();
    k_degcnt<<<nblkE, TB>>>(ei, w);
    k_norminv<<<nblkN, TB>>>();
    k_scan1<<<NBLK, SCAN_B>>>();
    k_scan2<<<1, 32>>>();
    k_scan3<<<nblkN, TB>>>();
    k_scatter<<<nblkE, TB>>>(ei, w);

    // --- layer 0 GEMM -> buf0 ---
    k_gemm0<<<(NN + 15) / 16, 256>>>(x, W0);

    // --- 12 fused agg+gemm layers (ping-pong buf0 <-> buf1) ---
    // fused l: agg with bias of conv l, then multiply by W of conv l+1
    k_fused<HID><<<nblk4, TB>>>(b0, Wmid, 0);                       // l=0
    for (int l = 1; l <= 10; l++) {
        k_fused<HID><<<nblk4, TB>>>(bmid + (size_t)(l - 1) * HID,
                                    Wmid + (size_t)l * HID * HID, l & 1);
    }
    k_fused<DOUT><<<nblk4, TB>>>(bmid + (size_t)10 * HID, Wlast, 1); // l=11 -> buf0

    // --- final aggregation (conv 12) straight into d_out ---
    k_agg_last<<<nblk4, TB>>>(blast, out);
}

// round 7
// speedup vs baseline: 1.3289x; 1.0030x over previous
#include <cuda_runtime.h>
#include <cuda_bf16.h>
#include <cstdint>

// Problem constants (fixed by the dataset)
static constexpr int NN    = 100000;   // nodes
static constexpr int EE    = 3200000;  // edges
static constexpr int DIN   = 128;
static constexpr int HID   = 16;
static constexpr int DOUT  = 12;
static constexpr int NMID  = 11;

static constexpr int SCAN_B = 1024;
static constexpr int NBLK   = (NN + SCAN_B - 1) / SCAN_B;   // 98

// ---------------- scratch (device globals; referenced only in device code) --
__device__ int    g_is64;
__device__ float  g_deg[NN];
__device__ float  g_dis[NN];       // rsqrt(deg)
__device__ float  g_selfw[NN];     // 1/deg
__device__ int    g_cnt[NN];       // histogram, then fill counters
__device__ int    g_ptr[NN + 1];   // CSR row (by dst) pointers
__device__ int    g_bsum[128];
__device__ int    g_dhist[256];    // degree histogram (clamped at 255)
__device__ int    g_doff[256];     // degree bucket offsets
__device__ int4   g_ninfo[NN];     // degree-sorted {start, end, selfw_bits, node}
__device__ float2 g_edge[EE];      // packed {src_as_float_bits, norm}
__device__ float  g_buf0[NN * HID];
__device__ float  g_buf1[NN * HID];

// ---------------- helpers ---------------------------------------------------
__device__ __forceinline__ int eidx(const void* ei, bool is64, long long i) {
    if (is64) return (int)((const long long*)ei)[i];
    return ((const int*)ei)[i];
}

// init: zero deg/cnt; block 0 also detects int64-vs-int32 and zeroes dhist.
// (int64 values < 2^31 -> every odd 32-bit word is a zero high-word)
__global__ void k_init(const unsigned int* p) {
    int i = blockIdx.x * blockDim.x + threadIdx.x;
    if (i < NN) { g_deg[i] = 0.f; g_cnt[i] = 0; }
    if (blockIdx.x == 0) {
        __shared__ unsigned int s_or;
        if (threadIdx.x == 0) s_or = 0u;
        __syncthreads();
        unsigned int acc = 0;
        for (int j = threadIdx.x; j < 1024; j += blockDim.x)
            acc |= p[2 * j + 1];
        if (acc) atomicOr(&s_or, acc);
        __syncthreads();
        if (threadIdx.x == 0) g_is64 = (s_or == 0u) ? 1 : 0;
        if (threadIdx.x < 256) g_dhist[threadIdx.x] = 0;
    }
}

__global__ void k_degcnt(const void* ei, const float* __restrict__ w) {
    bool is64 = (g_is64 != 0);
    for (int e = blockIdx.x * blockDim.x + threadIdx.x; e < EE;
         e += gridDim.x * blockDim.x) {
        int c = eidx(ei, is64, (long long)EE + e);
        atomicAdd(&g_deg[c], w[e]);
        atomicAdd(&g_cnt[c], 1);
    }
}

// scan1: block-level exclusive scan of cnt -> ptr; fold in norminv and a
// shared-memory degree histogram (merged to global with <=256 atomics/block).
__global__ void k_scan1() {
    __shared__ int s[SCAN_B];
    __shared__ int sh[256];
    int tid = threadIdx.x;
    if (tid < 256) sh[tid] = 0;
    int i = blockIdx.x * SCAN_B + tid;
    int v = (i < NN) ? g_cnt[i] : 0;
    s[tid] = v;
    __syncthreads();
    for (int off = 1; off < SCAN_B; off <<= 1) {
        int t = (tid >= off) ? s[tid - off] : 0;
        __syncthreads();
        s[tid] += t;
        __syncthreads();
    }
    if (i < NN) {
        g_ptr[i] = s[tid] - v;   // exclusive within block
        float d = g_deg[i] + 1.0f;
        g_dis[i]   = rsqrtf(d);
        g_selfw[i] = 1.0f / d;
        atomicAdd(&sh[v < 255 ? v : 255], 1);
    }
    if (tid == SCAN_B - 1) g_bsum[blockIdx.x] = s[SCAN_B - 1];
    __syncthreads();
    if (tid < 256 && sh[tid]) atomicAdd(&g_dhist[tid], sh[tid]);
}

// scan2: thread 0 serially scans the 98 block sums; 256 threads scan dhist.
__global__ void k_scan2() {
    __shared__ int s[256];
    int t = threadIdx.x;
    int v = g_dhist[t];
    s[t] = v;
    __syncthreads();
    for (int off = 1; off < 256; off <<= 1) {
        int x = (t >= off) ? s[t - off] : 0;
        __syncthreads();
        s[t] += x;
        __syncthreads();
    }
    g_doff[t] = s[t] - v;        // exclusive bucket offsets
    if (t == 0) {
        int acc = 0;
        for (int b = 0; b < NBLK; b++) { int tmpv = g_bsum[b]; g_bsum[b] = acc; acc += tmpv; }
    }
}

// scan3: finalize ptr; reset fill counters; counting-sort nodes by degree
// into g_ninfo as packed {start, end, selfw_bits, node}.
__global__ void k_scan3() {
    __shared__ int sh[256];
    __shared__ int base[256];
    int tid = threadIdx.x;
    if (tid < 256) sh[tid] = 0;
    __syncthreads();
    int i = blockIdx.x * SCAN_B + tid;
    bool act = (i < NN);
    int c = 0, d = 0, inblk = 0, p0 = 0;
    if (act) {
        c  = g_cnt[i];
        p0 = g_ptr[i] + g_bsum[blockIdx.x];
        g_ptr[i] = p0;
        g_cnt[i] = 0;                 // reuse as fill counters for scatter
        d = c < 255 ? c : 255;
        inblk = atomicAdd(&sh[d], 1);
    }
    __syncthreads();
    if (tid < 256) base[tid] = sh[tid] ? atomicAdd(&g_doff[tid], sh[tid]) : 0;
    __syncthreads();
    if (act) {
        int pos = base[d] + inblk;
        g_ninfo[pos] = make_int4(p0, p0 + c, __float_as_int(g_selfw[i]), i);
    }
}

// Scatter edges into CSR order (by destination) as packed {src, norm} (8B)
__global__ void k_scatter(const void* ei, const float* __restrict__ w) {
    bool is64 = (g_is64 != 0);
    for (int e = blockIdx.x * blockDim.x + threadIdx.x; e < EE;
         e += gridDim.x * blockDim.x) {
        int r = eidx(ei, is64, e);
        int c = eidx(ei, is64, (long long)EE + e);
        int pos = g_ptr[c] + atomicAdd(&g_cnt[c], 1);
        g_edge[pos] = make_float2(__int_as_float(r), g_dis[r] * w[e] * g_dis[c]);
    }
}

// ---------------- layer 0 GEMM: x[N,128] @ W0[128,16] -> g_buf0 -------------
__global__ void k_gemm0(const float* __restrict__ x, const float* __restrict__ W0) {
    __shared__ float Ws[DIN * HID];   // 8 KB
    __shared__ float xs[16 * DIN];    // 8 KB
    int tid = threadIdx.x;
    for (int i = tid; i < DIN * HID; i += 256) Ws[i] = W0[i];
    int n0 = blockIdx.x * 16;
    for (int i = tid; i < 16 * DIN; i += 256) {
        int nn = n0 + i / DIN;
        xs[i] = (nn < NN) ? x[(size_t)nn * DIN + (i % DIN)] : 0.f;
    }
    __syncthreads();
    int ln = tid >> 4, f = tid & 15;
    int n = n0 + ln;
    if (n < NN) {
        float acc = 0.f;
        #pragma unroll
        for (int k = 0; k < DIN; k++) acc += xs[ln * DIN + k] * Ws[k * HID + f];
        g_buf0[(size_t)n * HID + f] = acc;
    }
}

// ---------------- fused agg(+bias+relu) + next-layer GEMM -------------------
// Degree-sorted schedule: group g handles node g_ninfo[g].w; all lanes in a
// warp see near-equal edge counts, so the edge loop barely diverges.
template <int FOUT>
__global__ void __launch_bounds__(256) k_fused(const float* __restrict__ bias,
                                               const float* __restrict__ Wn, int rb) {
    __shared__ float Ws[HID * 16];
    int tid = threadIdx.x;
    for (int i = tid; i < HID * 16; i += 256) {
        int k = i >> 4, fo = i & 15;
        Ws[i] = (fo < FOUT) ? Wn[k * FOUT + fo] : 0.f;
    }
    __syncthreads();

    int gt  = blockIdx.x * blockDim.x + tid;
    int idx = gt >> 2;
    if (idx >= NN) idx = NN - 1;       // clamp: duplicate groups redo last node
    int l4 = tid & 3;

    int4  ni = g_ninfo[idx];           // broadcast LDG.128
    int   e = ni.x, end = ni.y, n = ni.w;
    float sw = __int_as_float(ni.z);

    const float4* __restrict__ tmp = rb ? (const float4*)g_buf1 : (const float4*)g_buf0;
    float4*       __restrict__ dst = rb ? (float4*)g_buf0       : (float4*)g_buf1;

    float4 t  = tmp[n * 4 + l4];
    float4 acc = make_float4(sw * t.x, sw * t.y, sw * t.z, sw * t.w);

    for (; e + 4 <= end; e += 4) {
        float2 e0 = g_edge[e],     e1 = g_edge[e + 1];
        float2 e2 = g_edge[e + 2], e3 = g_edge[e + 3];
        float4 v0 = tmp[__float_as_int(e0.x) * 4 + l4];
        float4 v1 = tmp[__float_as_int(e1.x) * 4 + l4];
        float4 v2 = tmp[__float_as_int(e2.x) * 4 + l4];
        float4 v3 = tmp[__float_as_int(e3.x) * 4 + l4];
        acc.x += e0.y * v0.x; acc.y += e0.y * v0.y; acc.z += e0.y * v0.z; acc.w += e0.y * v0.w;
        acc.x += e1.y * v1.x; acc.y += e1.y * v1.y; acc.z += e1.y * v1.z; acc.w += e1.y * v1.w;
        acc.x += e2.y * v2.x; acc.y += e2.y * v2.y; acc.z += e2.y * v2.z; acc.w += e2.y * v2.w;
        acc.x += e3.y * v3.x; acc.y += e3.y * v3.y; acc.z += e3.y * v3.z; acc.w += e3.y * v3.w;
    }
    for (; e < end; e++) {
        float2 ed = g_edge[e];
        float4 v  = tmp[__float_as_int(ed.x) * 4 + l4];
        acc.x += ed.y * v.x; acc.y += ed.y * v.y; acc.z += ed.y * v.z; acc.w += ed.y * v.w;
    }

    float4 b = ((const float4*)bias)[l4];   // agg layer feat dim is 16 here
    float4 h;
    h.x = fmaxf(acc.x + b.x, 0.f);
    h.y = fmaxf(acc.y + b.y, 0.f);
    h.z = fmaxf(acc.z + b.z, 0.f);
    h.w = fmaxf(acc.w + b.w, 0.f);

    // gather the full 16-feat row within the 4-lane group
    float hrow[16];
    int base = (tid & 31) & ~3;
    #pragma unroll
    for (int q = 0; q < 4; q++) {
        hrow[4 * q + 0] = __shfl_sync(0xffffffffu, h.x, base + q);
        hrow[4 * q + 1] = __shfl_sync(0xffffffffu, h.y, base + q);
        hrow[4 * q + 2] = __shfl_sync(0xffffffffu, h.z, base + q);
        hrow[4 * q + 3] = __shfl_sync(0xffffffffu, h.w, base + q);
    }

    float4 o = make_float4(0.f, 0.f, 0.f, 0.f);
    #pragma unroll
    for (int k = 0; k < HID; k++) {
        float hk = hrow[k];
        const float* wr = &Ws[k * 16 + l4 * 4];
        o.x += hk * wr[0]; o.y += hk * wr[1]; o.z += hk * wr[2]; o.w += hk * wr[3];
    }
    dst[n * 4 + l4] = o;    // duplicate clamped groups write identical values
}

// ---------------- final aggregation (F=12) into harness out -----------------
// tmp rows are stride-16 (cols 12..15 are zero-padded by k_fused<12>).
__global__ void __launch_bounds__(256) k_agg_last(const float* __restrict__ bias,
                                                  float* __restrict__ outp) {
    int gt  = blockIdx.x * blockDim.x + threadIdx.x;
    int idx = gt >> 2;
    if (idx >= NN) idx = NN - 1;
    int l4 = threadIdx.x & 3;

    int4  ni = g_ninfo[idx];
    int   e = ni.x, end = ni.y, n = ni.w;
    float sw = __int_as_float(ni.z);

    const float4* __restrict__ tmp = (const float4*)g_buf0;  // 12 fused layers end in buf0

    float4 t  = tmp[n * 4 + l4];
    float4 acc = make_float4(sw * t.x, sw * t.y, sw * t.z, sw * t.w);

    for (; e + 4 <= end; e += 4) {
        float2 e0 = g_edge[e],     e1 = g_edge[e + 1];
        float2 e2 = g_edge[e + 2], e3 = g_edge[e + 3];
        float4 v0 = tmp[__float_as_int(e0.x) * 4 + l4];
        float4 v1 = tmp[__float_as_int(e1.x) * 4 + l4];
        float4 v2 = tmp[__float_as_int(e2.x) * 4 + l4];
        float4 v3 = tmp[__float_as_int(e3.x) * 4 + l4];
        acc.x += e0.y * v0.x; acc.y += e0.y * v0.y; acc.z += e0.y * v0.z; acc.w += e0.y * v0.w;
        acc.x += e1.y * v1.x; acc.y += e1.y * v1.y; acc.z += e1.y * v1.z; acc.w += e1.y * v1.w;
        acc.x += e2.y * v2.x; acc.y += e2.y * v2.y; acc.z += e2.y * v2.z; acc.w += e2.y * v2.w;
        acc.x += e3.y * v3.x; acc.y += e3.y * v3.y; acc.z += e3.y * v3.z; acc.w += e3.y * v3.w;
    }
    for (; e < end; e++) {
        float2 ed = g_edge[e];
        float4 v  = tmp[__float_as_int(ed.x) * 4 + l4];
        acc.x += ed.y * v.x; acc.y += ed.y * v.y; acc.z += ed.y * v.z; acc.w += ed.y * v.w;
    }

    if (l4 < 3) {   // only feats 0..11 exist
        float4 b = *(const float4*)(bias + 4 * l4);
        float4 r;
        r.x = fmaxf(acc.x + b.x, 0.f);
        r.y = fmaxf(acc.y + b.y, 0.f);
        r.z = fmaxf(acc.z + b.z, 0.f);
        r.w = fmaxf(acc.w + b.w, 0.f);
        *(float4*)(outp + (size_t)n * DOUT + 4 * l4) = r;   // 48B rows: 16B-aligned
    }
}

// ---------------- launch ----------------------------------------------------
extern "C" void kernel_launch(void* const* d_in, const int* in_sizes, int n_in,
                              void* d_out, int out_size) {
    const float* x     = (const float*)d_in[0];
    const void*  ei    = d_in[1];
    const float* w     = (const float*)d_in[2];
    const float* W0    = (const float*)d_in[3];
    const float* b0    = (const float*)d_in[4];
    const float* Wmid  = (const float*)d_in[5];
    const float* bmid  = (const float*)d_in[6];
    const float* Wlast = (const float*)d_in[7];
    const float* blast = (const float*)d_in[8];
    float* out = (float*)d_out;

    const int TB = 256;
    const int nblkN = (NN + TB - 1) / TB;
    const int nblkE = 2048;
    const int nblk4 = (NN * 4 + TB - 1) / TB;   // 4 lanes/node

    // --- preprocessing ---
    k_init<<<nblkN, TB>>>((const unsigned int*)ei);
    k_degcnt<<<nblkE, TB>>>(ei, w);
    k_scan1<<<NBLK, SCAN_B>>>();
    k_scan2<<<1, 256>>>();
    k_scan3<<<NBLK, SCAN_B>>>();
    k_scatter<<<nblkE, TB>>>(ei, w);

    // --- layer 0 GEMM -> buf0 ---
    k_gemm0<<<(NN + 15) / 16, 256>>>(x, W0);

    // --- 12 fused agg+gemm layers (ping-pong buf0 <-> buf1) ---
    k_fused<HID><<<nblk4, TB>>>(b0, Wmid, 0);                        // l=0
    for (int l = 1; l <= 10; l++) {
        k_fused<HID><<<nblk4, TB>>>(bmid + (size_t)(l - 1) * HID,
                                    Wmid + (size_t)l * HID * HID, l & 1);
    }
    k_fused<DOUT><<<nblk4, TB>>>(bmid + (size_t)10 * HID, Wlast, 1); // l=11 -> buf0

    // --- final aggregation (conv 12) straight into d_out ---
    k_agg_last<<<nblk4, TB>>>(blast, out);
}

// round 8
// speedup vs baseline: 1.3827x; 1.0405x over previous
#include <cuda_runtime.h>
#include <cuda_bf16.h>
#include <cuda_fp16.h>
#include <cstdint>

// Problem constants (fixed by the dataset)
static constexpr int NN    = 100000;   // nodes
static constexpr int EE    = 3200000;  // edges
static constexpr int DIN   = 128;
static constexpr int HID   = 16;
static constexpr int DOUT  = 12;
static constexpr int NMID  = 11;

static constexpr int SCAN_B = 1024;
static constexpr int NBLK   = (NN + SCAN_B - 1) / SCAN_B;   // 98

// ---------------- scratch (device globals; referenced only in device code) --
__device__ int    g_is64;
__device__ float  g_deg[NN];
__device__ float  g_dis[NN];       // rsqrt(deg)
__device__ float  g_selfw[NN];     // 1/deg
__device__ int    g_cnt[NN];       // histogram, then fill counters
__device__ int    g_ptr[NN + 1];   // CSR row (by dst) pointers
__device__ int    g_bsum[128];
__device__ int    g_dhist[256];    // degree histogram (clamped at 255)
__device__ int    g_doff[256];     // degree bucket offsets
__device__ int4   g_ninfo[NN];     // degree-sorted {start, end, selfw_bits, node}
__device__ float2 g_edge[EE];      // packed {src_as_float_bits, norm}
__device__ uint4  g_hb0[NN * 2];   // fp16 features: 16 halves = 2x uint4 per node
__device__ uint4  g_hb1[NN * 2];

// ---------------- fp16 helpers ----------------------------------------------
__device__ __forceinline__ void cvt8(uint4 v, float* f) {
    __half2* hp = reinterpret_cast<__half2*>(&v);
    float2 a0 = __half22float2(hp[0]);
    float2 a1 = __half22float2(hp[1]);
    float2 a2 = __half22float2(hp[2]);
    float2 a3 = __half22float2(hp[3]);
    f[0] = a0.x; f[1] = a0.y; f[2] = a1.x; f[3] = a1.y;
    f[4] = a2.x; f[5] = a2.y; f[6] = a3.x; f[7] = a3.y;
}
__device__ __forceinline__ uint4 pack8(const float* o) {
    uint4 r;
    __half2 p0 = __floats2half2_rn(o[0], o[1]);
    __half2 p1 = __floats2half2_rn(o[2], o[3]);
    __half2 p2 = __floats2half2_rn(o[4], o[5]);
    __half2 p3 = __floats2half2_rn(o[6], o[7]);
    r.x = *reinterpret_cast<unsigned*>(&p0);
    r.y = *reinterpret_cast<unsigned*>(&p1);
    r.z = *reinterpret_cast<unsigned*>(&p2);
    r.w = *reinterpret_cast<unsigned*>(&p3);
    return r;
}

__device__ __forceinline__ int eidx(const void* ei, bool is64, long long i) {
    if (is64) return (int)((const long long*)ei)[i];
    return ((const int*)ei)[i];
}

// ---------------- preprocessing ---------------------------------------------
// init: zero deg/cnt; block 0 detects int64-vs-int32 and zeroes dhist.
__global__ void k_init(const unsigned int* p) {
    int i = blockIdx.x * blockDim.x + threadIdx.x;
    if (i < NN) { g_deg[i] = 0.f; g_cnt[i] = 0; }
    if (blockIdx.x == 0) {
        __shared__ unsigned int s_or;
        if (threadIdx.x == 0) s_or = 0u;
        __syncthreads();
        unsigned int acc = 0;
        for (int j = threadIdx.x; j < 1024; j += blockDim.x)
            acc |= p[2 * j + 1];
        if (acc) atomicOr(&s_or, acc);
        __syncthreads();
        if (threadIdx.x == 0) g_is64 = (s_or == 0u) ? 1 : 0;
        if (threadIdx.x < 256) g_dhist[threadIdx.x] = 0;
    }
}

__global__ void k_degcnt(const void* ei, const float* __restrict__ w) {
    bool is64 = (g_is64 != 0);
    for (int e = blockIdx.x * blockDim.x + threadIdx.x; e < EE;
         e += gridDim.x * blockDim.x) {
        int c = eidx(ei, is64, (long long)EE + e);
        atomicAdd(&g_deg[c], w[e]);
        atomicAdd(&g_cnt[c], 1);
    }
}

// scan1: block exclusive scan of cnt -> ptr; fold in norminv + degree histogram
__global__ void k_scan1() {
    __shared__ int s[SCAN_B];
    __shared__ int sh[256];
    int tid = threadIdx.x;
    if (tid < 256) sh[tid] = 0;
    int i = blockIdx.x * SCAN_B + tid;
    int v = (i < NN) ? g_cnt[i] : 0;
    s[tid] = v;
    __syncthreads();
    for (int off = 1; off < SCAN_B; off <<= 1) {
        int t = (tid >= off) ? s[tid - off] : 0;
        __syncthreads();
        s[tid] += t;
        __syncthreads();
    }
    if (i < NN) {
        g_ptr[i] = s[tid] - v;   // exclusive within block
        float d = g_deg[i] + 1.0f;
        g_dis[i]   = rsqrtf(d);
        g_selfw[i] = 1.0f / d;
        atomicAdd(&sh[v < 255 ? v : 255], 1);
    }
    if (tid == SCAN_B - 1) g_bsum[blockIdx.x] = s[SCAN_B - 1];
    __syncthreads();
    if (tid < 256 && sh[tid]) atomicAdd(&g_dhist[tid], sh[tid]);
}

// scan2: thread 0 scans block sums; 256 threads scan dhist.
__global__ void k_scan2() {
    __shared__ int s[256];
    int t = threadIdx.x;
    int v = g_dhist[t];
    s[t] = v;
    __syncthreads();
    for (int off = 1; off < 256; off <<= 1) {
        int x = (t >= off) ? s[t - off] : 0;
        __syncthreads();
        s[t] += x;
        __syncthreads();
    }
    g_doff[t] = s[t] - v;        // exclusive bucket offsets
    if (t == 0) {
        int acc = 0;
        for (int b = 0; b < NBLK; b++) { int tmpv = g_bsum[b]; g_bsum[b] = acc; acc += tmpv; }
    }
}

// scan3: finalize ptr; reset fill counters; counting-sort nodes by degree.
__global__ void k_scan3() {
    __shared__ int sh[256];
    __shared__ int base[256];
    int tid = threadIdx.x;
    if (tid < 256) sh[tid] = 0;
    __syncthreads();
    int i = blockIdx.x * SCAN_B + tid;
    bool act = (i < NN);
    int c = 0, d = 0, inblk = 0, p0 = 0;
    if (act) {
        c  = g_cnt[i];
        p0 = g_ptr[i] + g_bsum[blockIdx.x];
        g_ptr[i] = p0;
        g_cnt[i] = 0;                 // reuse as fill counters for scatter
        d = c < 255 ? c : 255;
        inblk = atomicAdd(&sh[d], 1);
    }
    __syncthreads();
    if (tid < 256) base[tid] = sh[tid] ? atomicAdd(&g_doff[tid], sh[tid]) : 0;
    __syncthreads();
    if (act) {
        int pos = base[d] + inblk;
        g_ninfo[pos] = make_int4(p0, p0 + c, __float_as_int(g_selfw[i]), i);
    }
}

// Scatter edges into CSR order (by destination) as packed {src, norm}
__global__ void k_scatter(const void* ei, const float* __restrict__ w) {
    bool is64 = (g_is64 != 0);
    for (int e = blockIdx.x * blockDim.x + threadIdx.x; e < EE;
         e += gridDim.x * blockDim.x) {
        int r = eidx(ei, is64, e);
        int c = eidx(ei, is64, (long long)EE + e);
        int pos = g_ptr[c] + atomicAdd(&g_cnt[c], 1);
        g_edge[pos] = make_float2(__int_as_float(r), g_dis[r] * w[e] * g_dis[c]);
    }
}

// ---------------- layer 0 GEMM: x[N,128] @ W0[128,16] -> g_hb0 (fp16) -------
__global__ void k_gemm0(const float* __restrict__ x, const float* __restrict__ W0) {
    __shared__ float Ws[DIN * HID];   // 8 KB
    __shared__ float xs[16 * DIN];    // 8 KB
    int tid = threadIdx.x;
    for (int i = tid; i < DIN * HID; i += 256) Ws[i] = W0[i];
    int n0 = blockIdx.x * 16;
    for (int i = tid; i < 16 * DIN; i += 256) {
        int nn = n0 + i / DIN;
        xs[i] = (nn < NN) ? x[(size_t)nn * DIN + (i % DIN)] : 0.f;
    }
    __syncthreads();
    int ln = tid >> 4, f = tid & 15;
    int n = n0 + ln;
    if (n < NN) {
        float acc = 0.f;
        #pragma unroll
        for (int k = 0; k < DIN; k++) acc += xs[ln * DIN + k] * Ws[k * HID + f];
        reinterpret_cast<__half*>(g_hb0)[n * HID + f] = __float2half_rn(acc);
    }
}

// ---------------- fused agg(+bias+relu) + next-layer GEMM (fp16 storage) ----
// 2 lanes per node; lane owns 8 feats (uint4 of halves). Degree-sorted order.
template <int FOUT>
__global__ void __launch_bounds__(256) k_fused(const float* __restrict__ bias,
                                               const float* __restrict__ Wn, int rb) {
    __shared__ float Ws[HID * 16];
    int tid = threadIdx.x;
    for (int i = tid; i < HID * 16; i += 256) {
        int k = i >> 4, fo = i & 15;
        Ws[i] = (fo < FOUT) ? Wn[k * FOUT + fo] : 0.f;
    }
    __syncthreads();

    int gt  = blockIdx.x * blockDim.x + tid;
    int idx = gt >> 1;
    if (idx >= NN) idx = NN - 1;       // clamp: duplicate pairs redo last node
    int l2 = tid & 1;

    int4  ni = g_ninfo[idx];           // broadcast LDG.128
    int   e = ni.x, end = ni.y, n = ni.w;
    float sw = __int_as_float(ni.z);

    const uint4* __restrict__ tmp = rb ? g_hb1 : g_hb0;
    uint4*       __restrict__ dst = rb ? g_hb0 : g_hb1;

    float acc[8], f0[8];
    cvt8(tmp[n * 2 + l2], f0);
    #pragma unroll
    for (int j = 0; j < 8; j++) acc[j] = sw * f0[j];

    for (; e + 4 <= end; e += 4) {
        float2 e0 = g_edge[e],     e1 = g_edge[e + 1];
        float2 e2 = g_edge[e + 2], e3 = g_edge[e + 3];
        uint4 v0 = tmp[__float_as_int(e0.x) * 2 + l2];
        uint4 v1 = tmp[__float_as_int(e1.x) * 2 + l2];
        uint4 v2 = tmp[__float_as_int(e2.x) * 2 + l2];
        uint4 v3 = tmp[__float_as_int(e3.x) * 2 + l2];
        float fa[8], fb[8], fc[8], fd[8];
        cvt8(v0, fa); cvt8(v1, fb); cvt8(v2, fc); cvt8(v3, fd);
        #pragma unroll
        for (int j = 0; j < 8; j++) {
            acc[j] += e0.y * fa[j];
            acc[j] += e1.y * fb[j];
            acc[j] += e2.y * fc[j];
            acc[j] += e3.y * fd[j];
        }
    }
    for (; e < end; e++) {
        float2 ed = g_edge[e];
        float fv[8];
        cvt8(tmp[__float_as_int(ed.x) * 2 + l2], fv);
        #pragma unroll
        for (int j = 0; j < 8; j++) acc[j] += ed.y * fv[j];
    }

    // bias + relu (agg feat dim is 16 on all fused layers)
    float4 ba = *(const float4*)(bias + l2 * 8);
    float4 bb = *(const float4*)(bias + l2 * 8 + 4);
    float h[8];
    h[0] = fmaxf(acc[0] + ba.x, 0.f); h[1] = fmaxf(acc[1] + ba.y, 0.f);
    h[2] = fmaxf(acc[2] + ba.z, 0.f); h[3] = fmaxf(acc[3] + ba.w, 0.f);
    h[4] = fmaxf(acc[4] + bb.x, 0.f); h[5] = fmaxf(acc[5] + bb.y, 0.f);
    h[6] = fmaxf(acc[6] + bb.z, 0.f); h[7] = fmaxf(acc[7] + bb.w, 0.f);

    // reconstruct the full 16-feat row within the 2-lane pair
    float hrow[16];
    #pragma unroll
    for (int j = 0; j < 8; j++) {
        float pj = __shfl_xor_sync(0xffffffffu, h[j], 1);
        hrow[l2 * 8 + j]       = h[j];
        hrow[(1 - l2) * 8 + j] = pj;
    }

    // next-layer GEMM: this lane produces output feats l2*8 .. l2*8+7
    float o[8] = {0, 0, 0, 0, 0, 0, 0, 0};
    #pragma unroll
    for (int k = 0; k < HID; k++) {
        float hk = hrow[k];
        const float* wr = &Ws[k * 16 + l2 * 8];
        #pragma unroll
        for (int j = 0; j < 8; j++) o[j] += hk * wr[j];
    }
    dst[n * 2 + l2] = pack8(o);   // duplicate clamped pairs write identical data
}

// ---------------- final aggregation (F=12) into harness out (fp32) ----------
// tmp rows are stride-16 halves (cols 12..15 zero-padded by k_fused<12>).
__global__ void __launch_bounds__(256) k_agg_last(const float* __restrict__ bias,
                                                  float* __restrict__ outp) {
    int gt  = blockIdx.x * blockDim.x + threadIdx.x;
    int idx = gt >> 1;
    if (idx >= NN) idx = NN - 1;
    int l2 = threadIdx.x & 1;

    int4  ni = g_ninfo[idx];
    int   e = ni.x, end = ni.y, n = ni.w;
    float sw = __int_as_float(ni.z);

    const uint4* __restrict__ tmp = g_hb0;   // 12 fused layers end in hb0

    float acc[8], f0[8];
    cvt8(tmp[n * 2 + l2], f0);
    #pragma unroll
    for (int j = 0; j < 8; j++) acc[j] = sw * f0[j];

    for (; e + 4 <= end; e += 4) {
        float2 e0 = g_edge[e],     e1 = g_edge[e + 1];
        float2 e2 = g_edge[e + 2], e3 = g_edge[e + 3];
        uint4 v0 = tmp[__float_as_int(e0.x) * 2 + l2];
        uint4 v1 = tmp[__float_as_int(e1.x) * 2 + l2];
        uint4 v2 = tmp[__float_as_int(e2.x) * 2 + l2];
        uint4 v3 = tmp[__float_as_int(e3.x) * 2 + l2];
        float fa[8], fb[8], fc[8], fd[8];
        cvt8(v0, fa); cvt8(v1, fb); cvt8(v2, fc); cvt8(v3, fd);
        #pragma unroll
        for (int j = 0; j < 8; j++) {
            acc[j] += e0.y * fa[j];
            acc[j] += e1.y * fb[j];
            acc[j] += e2.y * fc[j];
            acc[j] += e3.y * fd[j];
        }
    }
    for (; e < end; e++) {
        float2 ed = g_edge[e];
        float fv[8];
        cvt8(tmp[__float_as_int(ed.x) * 2 + l2], fv);
        #pragma unroll
        for (int j = 0; j < 8; j++) acc[j] += ed.y * fv[j];
    }

    if (l2 == 0) {          // feats 0..7
        float4 b0v = *(const float4*)(bias);
        float4 b1v = *(const float4*)(bias + 4);
        float4 r0, r1;
        r0.x = fmaxf(acc[0] + b0v.x, 0.f); r0.y = fmaxf(acc[1] + b0v.y, 0.f);
        r0.z = fmaxf(acc[2] + b0v.z, 0.f); r0.w = fmaxf(acc[3] + b0v.w, 0.f);
        r1.x = fmaxf(acc[4] + b1v.x, 0.f); r1.y = fmaxf(acc[5] + b1v.y, 0.f);
        r1.z = fmaxf(acc[6] + b1v.z, 0.f); r1.w = fmaxf(acc[7] + b1v.w, 0.f);
        *(float4*)(outp + (size_t)n * DOUT)     = r0;
        *(float4*)(outp + (size_t)n * DOUT + 4) = r1;
    } else {                // feats 8..11 (12..15 are padding)
        float4 b2v = *(const float4*)(bias + 8);
        float4 r2;
        r2.x = fmaxf(acc[0] + b2v.x, 0.f); r2.y = fmaxf(acc[1] + b2v.y, 0.f);
        r2.z = fmaxf(acc[2] + b2v.z, 0.f); r2.w = fmaxf(acc[3] + b2v.w, 0.f);
        *(float4*)(outp + (size_t)n * DOUT + 8) = r2;
    }
}

// ---------------- launch ----------------------------------------------------
extern "C" void kernel_launch(void* const* d_in, const int* in_sizes, int n_in,
                              void* d_out, int out_size) {
    const float* x     = (const float*)d_in[0];
    const void*  ei    = d_in[1];
    const float* w     = (const float*)d_in[2];
    const float* W0    = (const float*)d_in[3];
    const float* b0    = (const float*)d_in[4];
    const float* Wmid  = (const float*)d_in[5];
    const float* bmid  = (const float*)d_in[6];
    const float* Wlast = (const float*)d_in[7];
    const float* blast = (const float*)d_in[8];
    float* out = (float*)d_out;

    const int TB = 256;
    const int nblkN = (NN + TB - 1) / TB;
    const int nblkE = 2048;
    const int nblk2 = (NN * 2 + TB - 1) / TB;   // 2 lanes/node

    // --- preprocessing ---
    k_init<<<nblkN, TB>>>((const unsigned int*)ei);
    k_degcnt<<<nblkE, TB>>>(ei, w);
    k_scan1<<<NBLK, SCAN_B>>>();
    k_scan2<<<1, 256>>>();
    k_scan3<<<NBLK, SCAN_B>>>();
    k_scatter<<<nblkE, TB>>>(ei, w);

    // --- layer 0 GEMM -> hb0 (fp16) ---
    k_gemm0<<<(NN + 15) / 16, 256>>>(x, W0);

    // --- 12 fused agg+gemm layers (ping-pong hb0 <-> hb1) ---
    k_fused<HID><<<nblk2, TB>>>(b0, Wmid, 0);                        // l=0
    for (int l = 1; l <= 10; l++) {
        k_fused<HID><<<nblk2, TB>>>(bmid + (size_t)(l - 1) * HID,
                                    Wmid + (size_t)l * HID * HID, l & 1);
    }
    k_fused<DOUT><<<nblk2, TB>>>(bmid + (size_t)10 * HID, Wlast, 1); // l=11 -> hb0

    // --- final aggregation (conv 12) straight into d_out (fp32) ---
    k_agg_last<<<nblk2, TB>>>(blast, out);
}

// round 9
// speedup vs baseline: 1.4334x; 1.0366x over previous
#include <cuda_runtime.h>
#include <cuda_bf16.h>
#include <cuda_fp16.h>
#include <cstdint>

// Problem constants (fixed by the dataset)
static constexpr int NN    = 100000;   // nodes
static constexpr int EE    = 3200000;  // edges
static constexpr int DIN   = 128;
static constexpr int HID   = 16;
static constexpr int DOUT  = 12;
static constexpr int NMID  = 11;

static constexpr int NGRP  = (NN + 15) / 16;         // 6250 warp-groups of 16 nodes
static constexpr int ECAP  = EE + 64 * NGRP;         // transposed slots incl. padding

// ---------------- scratch (device globals; referenced only in device code) --
__device__ int    g_is64;
__device__ float  g_deg[NN];
__device__ float  g_dis[NN];        // rsqrt(deg)
__device__ float  g_selfw[NN];      // 1/deg
__device__ int    g_cnt[NN];        // edge count, then fill counters
__device__ int    g_dhist[256];     // degree histogram (clamped at 255)
__device__ int    g_doff[256];      // degree bucket offsets
__device__ int2   g_snode[NN];      // sorted: {node, selfw_bits}
__device__ int    g_sdeg[NN];       // sorted: edge count
__device__ int    g_sortpos[NN];    // node -> sorted position
__device__ int    g_gdeg[NGRP];     // per-group max degree
__device__ int    g_goff[NGRP + 1]; // group slot offsets (slots, = 16*sum(maxdeg))
__device__ float2 g_edge2[ECAP];    // transposed: slot goff[g]+k*16+p = edge k of member p
__device__ uint4  g_hb0[NN * 2];    // fp16 features: 16 halves = 2x uint4 per node
__device__ uint4  g_hb1[NN * 2];

// ---------------- fp16 helpers ----------------------------------------------
__device__ __forceinline__ void cvt8(uint4 v, float* f) {
    __half2* hp = reinterpret_cast<__half2*>(&v);
    float2 a0 = __half22float2(hp[0]);
    float2 a1 = __half22float2(hp[1]);
    float2 a2 = __half22float2(hp[2]);
    float2 a3 = __half22float2(hp[3]);
    f[0] = a0.x; f[1] = a0.y; f[2] = a1.x; f[3] = a1.y;
    f[4] = a2.x; f[5] = a2.y; f[6] = a3.x; f[7] = a3.y;
}
__device__ __forceinline__ uint4 pack8(const float* o) {
    uint4 r;
    __half2 p0 = __floats2half2_rn(o[0], o[1]);
    __half2 p1 = __floats2half2_rn(o[2], o[3]);
    __half2 p2 = __floats2half2_rn(o[4], o[5]);
    __half2 p3 = __floats2half2_rn(o[6], o[7]);
    r.x = *reinterpret_cast<unsigned*>(&p0);
    r.y = *reinterpret_cast<unsigned*>(&p1);
    r.z = *reinterpret_cast<unsigned*>(&p2);
    r.w = *reinterpret_cast<unsigned*>(&p3);
    return r;
}

__device__ __forceinline__ int eidx(const void* ei, bool is64, long long i) {
    if (is64) return (int)((const long long*)ei)[i];
    return ((const int*)ei)[i];
}

// ---------------- preprocessing ---------------------------------------------
// init: zero deg/cnt; block 0 detects int64-vs-int32 and zeroes dhist.
__global__ void k_init(const unsigned int* p) {
    int i = blockIdx.x * blockDim.x + threadIdx.x;
    if (i < NN) { g_deg[i] = 0.f; g_cnt[i] = 0; }
    if (blockIdx.x == 0) {
        __shared__ unsigned int s_or;
        if (threadIdx.x == 0) s_or = 0u;
        __syncthreads();
        unsigned int acc = 0;
        for (int j = threadIdx.x; j < 1024; j += blockDim.x)
            acc |= p[2 * j + 1];
        if (acc) atomicOr(&s_or, acc);
        __syncthreads();
        if (threadIdx.x == 0) g_is64 = (s_or == 0u) ? 1 : 0;
        if (threadIdx.x < 256) g_dhist[threadIdx.x] = 0;
    }
}

__global__ void k_degcnt(const void* ei, const float* __restrict__ w) {
    bool is64 = (g_is64 != 0);
    for (int e = blockIdx.x * blockDim.x + threadIdx.x; e < EE;
         e += gridDim.x * blockDim.x) {
        int c = eidx(ei, is64, (long long)EE + e);
        atomicAdd(&g_deg[c], w[e]);
        atomicAdd(&g_cnt[c], 1);
    }
}

// norminv + shared-memory degree histogram
__global__ void k_normhist() {
    __shared__ int sh[256];
    int tid = threadIdx.x;
    sh[tid] = 0;
    __syncthreads();
    int i = blockIdx.x * blockDim.x + tid;
    if (i < NN) {
        float d = g_deg[i] + 1.0f;
        g_dis[i]   = rsqrtf(d);
        g_selfw[i] = 1.0f / d;
        int v = g_cnt[i];
        atomicAdd(&sh[v < 255 ? v : 255], 1);
    }
    __syncthreads();
    if (sh[tid]) atomicAdd(&g_dhist[tid], sh[tid]);
}

// scan dhist -> doff (1 block, 256 threads)
__global__ void k_scanh() {
    __shared__ int s[256];
    int t = threadIdx.x;
    int v = g_dhist[t];
    s[t] = v;
    __syncthreads();
    for (int off = 1; off < 256; off <<= 1) {
        int x = (t >= off) ? s[t - off] : 0;
        __syncthreads();
        s[t] += x;
        __syncthreads();
    }
    g_doff[t] = s[t] - v;        // exclusive bucket offsets
}

// counting-sort nodes by degree; record node->pos and sorted metadata
__global__ void k_sort() {
    __shared__ int sh[256];
    __shared__ int base[256];
    int tid = threadIdx.x;
    if (tid < 256) sh[tid] = 0;
    __syncthreads();
    int i = blockIdx.x * 1024 + tid;
    bool act = (i < NN);
    int c = 0, d = 0, inblk = 0;
    if (act) {
        c = g_cnt[i];
        g_cnt[i] = 0;                 // reuse as fill counters for scatter
        d = c < 255 ? c : 255;
        inblk = atomicAdd(&sh[d], 1);
    }
    __syncthreads();
    if (tid < 256) base[tid] = sh[tid] ? atomicAdd(&g_doff[tid], sh[tid]) : 0;
    __syncthreads();
    if (act) {
        int pos = base[d] + inblk;
        g_snode[pos]  = make_int2(i, __float_as_int(g_selfw[i]));
        g_sdeg[pos]   = c;
        g_sortpos[i]  = pos;
    }
}

// per-group max degree (robust to unsorted clamp bucket)
__global__ void k_gmax() {
    int g = blockIdx.x * blockDim.x + threadIdx.x;
    if (g >= NGRP) return;
    int m = 0;
    #pragma unroll
    for (int j = 0; j < 16; j++) {
        int pos = g * 16 + j;
        if (pos < NN) { int c = g_sdeg[pos]; m = c > m ? c : m; }
    }
    g_gdeg[g] = m;
}

// scan group slot sizes -> g_goff (1 block, 1024 threads, chunked with carry)
__global__ void k_gscan() {
    __shared__ int s[1024];
    __shared__ int carry;
    int tid = threadIdx.x;
    if (tid == 0) { carry = 0; g_goff[0] = 0; }
    __syncthreads();
    for (int c0 = 0; c0 < NGRP; c0 += 1024) {
        int g = c0 + tid;
        int v = (g < NGRP) ? 16 * g_gdeg[g] : 0;
        s[tid] = v;
        __syncthreads();
        for (int off = 1; off < 1024; off <<= 1) {
            int x = (tid >= off) ? s[tid - off] : 0;
            __syncthreads();
            s[tid] += x;
            __syncthreads();
        }
        if (g < NGRP) g_goff[g + 1] = carry + s[tid];
        __syncthreads();
        if (tid == 1023) carry += s[1023];
        __syncthreads();
    }
}

// fill padding slots with {src=0, norm=0}
__global__ void k_pad() {
    int pos = blockIdx.x * blockDim.x + threadIdx.x;
    if (pos >= NN) return;
    int g = pos >> 4, lane = pos & 15;
    int c = g_sdeg[pos];
    int base = g_goff[g];
    int K = (g_goff[g + 1] - base) >> 4;
    for (int k = c; k < K; k++)
        g_edge2[base + k * 16 + lane] = make_float2(__int_as_float(0), 0.f);
}

// scatter edges into the transposed layout
__global__ void k_scatter(const void* ei, const float* __restrict__ w) {
    bool is64 = (g_is64 != 0);
    for (int e = blockIdx.x * blockDim.x + threadIdx.x; e < EE;
         e += gridDim.x * blockDim.x) {
        int r = eidx(ei, is64, e);
        int c = eidx(ei, is64, (long long)EE + e);
        int k   = atomicAdd(&g_cnt[c], 1);
        int sp  = g_sortpos[c];
        int slot = g_goff[sp >> 4] + k * 16 + (sp & 15);
        g_edge2[slot] = make_float2(__int_as_float(r), g_dis[r] * w[e] * g_dis[c]);
    }
}

// ---------------- layer 0 GEMM: x[N,128] @ W0[128,16] -> g_hb0 (fp16) -------
__global__ void k_gemm0(const float* __restrict__ x, const float* __restrict__ W0) {
    __shared__ float Ws[DIN * HID];   // 8 KB
    __shared__ float xs[16 * DIN];    // 8 KB
    int tid = threadIdx.x;
    for (int i = tid; i < DIN * HID; i += 256) Ws[i] = W0[i];
    int n0 = blockIdx.x * 16;
    for (int i = tid; i < 16 * DIN; i += 256) {
        int nn = n0 + i / DIN;
        xs[i] = (nn < NN) ? x[(size_t)nn * DIN + (i % DIN)] : 0.f;
    }
    __syncthreads();
    int ln = tid >> 4, f = tid & 15;
    int n = n0 + ln;
    if (n < NN) {
        float acc = 0.f;
        #pragma unroll
        for (int k = 0; k < DIN; k++) acc += xs[ln * DIN + k] * Ws[k * HID + f];
        reinterpret_cast<__half*>(g_hb0)[n * HID + f] = __float2half_rn(acc);
    }
}

// ---------------- fused agg(+bias+relu) + next-layer GEMM (fp16, transposed)-
// One warp per 16-node group; pair p (2 lanes) owns group member p. Edge meta
// loads are a single 128B line per step; feature gathers 1 line per edge.
template <int FOUT>
__global__ void __launch_bounds__(256) k_fused(const float* __restrict__ bias,
                                               const float* __restrict__ Wn, int rb) {
    __shared__ float Ws[HID * 16];
    int tid = threadIdx.x;
    for (int i = tid; i < HID * 16; i += 256) {
        int k = i >> 4, fo = i & 15;
        Ws[i] = (fo < FOUT) ? Wn[k * FOUT + fo] : 0.f;
    }
    __syncthreads();

    int g = (blockIdx.x * 256 + tid) >> 5;        // group = warp
    if (g >= NGRP) g = NGRP - 1;                  // dup warps redo last group
    int p  = (tid >> 1) & 15;
    int l2 = tid & 1;

    int2  sn = g_snode[g * 16 + p];
    int   n  = sn.x;
    float sw = __int_as_float(sn.y);
    int base = g_goff[g];
    int K    = (g_goff[g + 1] - base) >> 4;       // padded edges per member

    const uint4* __restrict__ tmp = rb ? g_hb1 : g_hb0;
    uint4*       __restrict__ dst = rb ? g_hb0 : g_hb1;

    float acc[8], f0[8];
    cvt8(tmp[n * 2 + l2], f0);
    #pragma unroll
    for (int j = 0; j < 8; j++) acc[j] = sw * f0[j];

    const float2* ep = g_edge2 + base + p;
    int k = 0;
    for (; k + 4 <= K; k += 4) {
        float2 e0 = ep[(k + 0) * 16], e1 = ep[(k + 1) * 16];
        float2 e2 = ep[(k + 2) * 16], e3 = ep[(k + 3) * 16];
        uint4 v0 = tmp[__float_as_int(e0.x) * 2 + l2];
        uint4 v1 = tmp[__float_as_int(e1.x) * 2 + l2];
        uint4 v2 = tmp[__float_as_int(e2.x) * 2 + l2];
        uint4 v3 = tmp[__float_as_int(e3.x) * 2 + l2];
        float fa[8], fb[8], fc[8], fd[8];
        cvt8(v0, fa); cvt8(v1, fb); cvt8(v2, fc); cvt8(v3, fd);
        #pragma unroll
        for (int j = 0; j < 8; j++) {
            acc[j] += e0.y * fa[j];
            acc[j] += e1.y * fb[j];
            acc[j] += e2.y * fc[j];
            acc[j] += e3.y * fd[j];
        }
    }
    for (; k < K; k++) {
        float2 ed = ep[k * 16];
        float fv[8];
        cvt8(tmp[__float_as_int(ed.x) * 2 + l2], fv);
        #pragma unroll
        for (int j = 0; j < 8; j++) acc[j] += ed.y * fv[j];
    }

    // bias + relu (agg feat dim is 16 on all fused layers)
    float4 ba = *(const float4*)(bias + l2 * 8);
    float4 bb = *(const float4*)(bias + l2 * 8 + 4);
    float h[8];
    h[0] = fmaxf(acc[0] + ba.x, 0.f); h[1] = fmaxf(acc[1] + ba.y, 0.f);
    h[2] = fmaxf(acc[2] + ba.z, 0.f); h[3] = fmaxf(acc[3] + ba.w, 0.f);
    h[4] = fmaxf(acc[4] + bb.x, 0.f); h[5] = fmaxf(acc[5] + bb.y, 0.f);
    h[6] = fmaxf(acc[6] + bb.z, 0.f); h[7] = fmaxf(acc[7] + bb.w, 0.f);

    // reconstruct the full 16-feat row within the 2-lane pair
    float hrow[16];
    #pragma unroll
    for (int j = 0; j < 8; j++) {
        float pj = __shfl_xor_sync(0xffffffffu, h[j], 1);
        hrow[l2 * 8 + j]       = h[j];
        hrow[(1 - l2) * 8 + j] = pj;
    }

    // next-layer GEMM: this lane produces output feats l2*8 .. l2*8+7
    float o[8] = {0, 0, 0, 0, 0, 0, 0, 0};
    #pragma unroll
    for (int kk = 0; kk < HID; kk++) {
        float hk = hrow[kk];
        const float* wr = &Ws[kk * 16 + l2 * 8];
        #pragma unroll
        for (int j = 0; j < 8; j++) o[j] += hk * wr[j];
    }
    dst[n * 2 + l2] = pack8(o);   // dup warps write identical data
}

// ---------------- final aggregation (F=12) into harness out (fp32) ----------
__global__ void __launch_bounds__(256) k_agg_last(const float* __restrict__ bias,
                                                  float* __restrict__ outp) {
    int g = (blockIdx.x * 256 + threadIdx.x) >> 5;
    if (g >= NGRP) g = NGRP - 1;
    int p  = (threadIdx.x >> 1) & 15;
    int l2 = threadIdx.x & 1;

    int2  sn = g_snode[g * 16 + p];
    int   n  = sn.x;
    float sw = __int_as_float(sn.y);
    int base = g_goff[g];
    int K    = (g_goff[g + 1] - base) >> 4;

    const uint4* __restrict__ tmp = g_hb0;   // 12 fused layers end in hb0

    float acc[8], f0[8];
    cvt8(tmp[n * 2 + l2], f0);
    #pragma unroll
    for (int j = 0; j < 8; j++) acc[j] = sw * f0[j];

    const float2* ep = g_edge2 + base + p;
    int k = 0;
    for (; k + 4 <= K; k += 4) {
        float2 e0 = ep[(k + 0) * 16], e1 = ep[(k + 1) * 16];
        float2 e2 = ep[(k + 2) * 16], e3 = ep[(k + 3) * 16];
        uint4 v0 = tmp[__float_as_int(e0.x) * 2 + l2];
        uint4 v1 = tmp[__float_as_int(e1.x) * 2 + l2];
        uint4 v2 = tmp[__float_as_int(e2.x) * 2 + l2];
        uint4 v3 = tmp[__float_as_int(e3.x) * 2 + l2];
        float fa[8], fb[8], fc[8], fd[8];
        cvt8(v0, fa); cvt8(v1, fb); cvt8(v2, fc); cvt8(v3, fd);
        #pragma unroll
        for (int j = 0; j < 8; j++) {
            acc[j] += e0.y * fa[j];
            acc[j] += e1.y * fb[j];
            acc[j] += e2.y * fc[j];
            acc[j] += e3.y * fd[j];
        }
    }
    for (; k < K; k++) {
        float2 ed = ep[k * 16];
        float fv[8];
        cvt8(tmp[__float_as_int(ed.x) * 2 + l2], fv);
        #pragma unroll
        for (int j = 0; j < 8; j++) acc[j] += ed.y * fv[j];
    }

    if (l2 == 0) {          // feats 0..7
        float4 b0v = *(const float4*)(bias);
        float4 b1v = *(const float4*)(bias + 4);
        float4 r0, r1;
        r0.x = fmaxf(acc[0] + b0v.x, 0.f); r0.y = fmaxf(acc[1] + b0v.y, 0.f);
        r0.z = fmaxf(acc[2] + b0v.z, 0.f); r0.w = fmaxf(acc[3] + b0v.w, 0.f);
        r1.x = fmaxf(acc[4] + b1v.x, 0.f); r1.y = fmaxf(acc[5] + b1v.y, 0.f);
        r1.z = fmaxf(acc[6] + b1v.z, 0.f); r1.w = fmaxf(acc[7] + b1v.w, 0.f);
        *(float4*)(outp + (size_t)n * DOUT)     = r0;
        *(float4*)(outp + (size_t)n * DOUT + 4) = r1;
    } else {                // feats 8..11 (12..15 are padding)
        float4 b2v = *(const float4*)(bias + 8);
        float4 r2;
        r2.x = fmaxf(acc[0] + b2v.x, 0.f); r2.y = fmaxf(acc[1] + b2v.y, 0.f);
        r2.z = fmaxf(acc[2] + b2v.z, 0.f); r2.w = fmaxf(acc[3] + b2v.w, 0.f);
        *(float4*)(outp + (size_t)n * DOUT + 8) = r2;
    }
}

// ---------------- launch ----------------------------------------------------
extern "C" void kernel_launch(void* const* d_in, const int* in_sizes, int n_in,
                              void* d_out, int out_size) {
    const float* x     = (const float*)d_in[0];
    const void*  ei    = d_in[1];
    const float* w     = (const float*)d_in[2];
    const float* W0    = (const float*)d_in[3];
    const float* b0    = (const float*)d_in[4];
    const float* Wmid  = (const float*)d_in[5];
    const float* bmid  = (const float*)d_in[6];
    const float* Wlast = (const float*)d_in[7];
    const float* blast = (const float*)d_in[8];
    float* out = (float*)d_out;

    const int TB = 256;
    const int nblkN = (NN + TB - 1) / TB;
    const int nblkE = 2048;
    const int nblkW = (NGRP * 32 + TB - 1) / TB;   // 1 warp per 16-node group

    // --- preprocessing ---
    k_init<<<nblkN, TB>>>((const unsigned int*)ei);
    k_degcnt<<<nblkE, TB>>>(ei, w);
    k_normhist<<<nblkN, TB>>>();
    k_scanh<<<1, 256>>>();
    k_sort<<<(NN + 1023) / 1024, 1024>>>();
    k_gmax<<<(NGRP + TB - 1) / TB, TB>>>();
    k_gscan<<<1, 1024>>>();
    k_pad<<<nblkN, TB>>>();
    k_scatter<<<nblkE, TB>>>(ei, w);

    // --- layer 0 GEMM -> hb0 (fp16) ---
    k_gemm0<<<(NN + 15) / 16, 256>>>(x, W0);

    // --- 12 fused agg+gemm layers (ping-pong hb0 <-> hb1) ---
    k_fused<HID><<<nblkW, TB>>>(b0, Wmid, 0);                        // l=0
    for (int l = 1; l <= 10; l++) {
        k_fused<HID><<<nblkW, TB>>>(bmid + (size_t)(l - 1) * HID,
                                    Wmid + (size_t)l * HID * HID, l & 1);
    }
    k_fused<DOUT><<<nblkW, TB>>>(bmid + (size_t)10 * HID, Wlast, 1); // l=11 -> hb0

    // --- final aggregation (conv 12) straight into d_out (fp32) ---
    k_agg_last<<<nblkW, TB>>>(blast, out);
}

// round 11
// speedup vs baseline: 1.5617x; 1.0895x over previous
#include <cuda_runtime.h>
#include <cuda_bf16.h>
#include <cuda_fp16.h>
#include <cstdint>

// Problem constants (fixed by the dataset)
static constexpr int NN    = 100000;   // nodes
static constexpr int EE    = 3200000;  // edges
static constexpr int DIN   = 128;
static constexpr int HID   = 16;
static constexpr int DOUT  = 12;
static constexpr int NMID  = 11;

static constexpr int NGRP  = (NN + 7) / 8;           // 12500 warp-groups of 8 nodes
static constexpr int ECAP  = EE + 64 * NGRP;         // transposed slots incl. padding

// ---------------- scratch (device globals; referenced only in device code) --
__device__ int                g_is64;
__device__ unsigned long long g_pk[NN];      // hi32 = count, lo32 = sum(w)*2^24
__device__ float  g_dis[NN];                 // rsqrt(deg)
__device__ float  g_selfw[NN];               // 1/deg
__device__ int    g_cnt[NN];                 // fill counters for scatter (zeroed at init)
__device__ int    g_dhist[256];              // degree histogram (clamped at 255)
__device__ int    g_doff[256];               // degree bucket offsets
__device__ int2   g_snode[NN];               // sorted: {node, selfw_bits}
__device__ int    g_sdeg[NN];                // sorted: edge count
__device__ int    g_sortpos[NN];             // node -> sorted position
__device__ int    g_gdeg[NGRP];              // per-group max degree
__device__ int    g_goff[NGRP + 1];          // group slot offsets (8*sum(maxdeg))
__device__ float2 g_edge2[ECAP];             // slot goff[g]+k*8+p = edge k of member p
__device__ uint2  g_hb0[NN * 4];             // fp16 features: 16 halves = 4x uint2/node
__device__ uint2  g_hb1[NN * 4];

// ---------------- fp16 helpers ----------------------------------------------
__device__ __forceinline__ void cvt4(uint2 v, float* f) {
    __half2 h0 = *reinterpret_cast<__half2*>(&v.x);
    __half2 h1 = *reinterpret_cast<__half2*>(&v.y);
    float2 a0 = __half22float2(h0);
    float2 a1 = __half22float2(h1);
    f[0] = a0.x; f[1] = a0.y; f[2] = a1.x; f[3] = a1.y;
}
__device__ __forceinline__ uint2 pack4(const float* o) {
    uint2 r;
    __half2 p0 = __floats2half2_rn(o[0], o[1]);
    __half2 p1 = __floats2half2_rn(o[2], o[3]);
    r.x = *reinterpret_cast<unsigned*>(&p0);
    r.y = *reinterpret_cast<unsigned*>(&p1);
    return r;
}

__device__ __forceinline__ int eidx(const void* ei, bool is64, long long i) {
    if (is64) return (int)((const long long*)ei)[i];
    return ((const int*)ei)[i];
}

// ---------------- preprocessing ---------------------------------------------
// init: zero pk/cnt; block 0 detects int64-vs-int32 and zeroes dhist.
__global__ void k_init(const unsigned int* p) {
    int i = blockIdx.x * blockDim.x + threadIdx.x;
    if (i < NN) { g_pk[i] = 0ull; g_cnt[i] = 0; }
    if (blockIdx.x == 0) {
        __shared__ unsigned int s_or;
        if (threadIdx.x == 0) s_or = 0u;
        __syncthreads();
        unsigned int acc = 0;
        for (int j = threadIdx.x; j < 1024; j += blockDim.x)
            acc |= p[2 * j + 1];
        if (acc) atomicOr(&s_or, acc);
        __syncthreads();
        if (threadIdx.x == 0) g_is64 = (s_or == 0u) ? 1 : 0;
        if (threadIdx.x < 256) g_dhist[threadIdx.x] = 0;
    }
}

// one packed 64-bit atomic per edge: count in hi32, fixed-point weight in lo32
__global__ void k_degcnt(const void* ei, const float* __restrict__ w) {
    bool is64 = (g_is64 != 0);
    for (int e = blockIdx.x * blockDim.x + threadIdx.x; e < EE;
         e += gridDim.x * blockDim.x) {
        int c = eidx(ei, is64, (long long)EE + e);
        unsigned int fx = (unsigned int)__float2uint_rn(w[e] * 16777216.f);
        atomicAdd(&g_pk[c], (1ull << 32) | (unsigned long long)fx);
    }
}

// norminv + shared-memory degree histogram
__global__ void k_normhist() {
    __shared__ int sh[256];
    int tid = threadIdx.x;
    sh[tid] = 0;
    __syncthreads();
    int i = blockIdx.x * blockDim.x + tid;
    if (i < NN) {
        unsigned long long pk = g_pk[i];
        int v = (int)(pk >> 32);
        float d = (float)(unsigned int)(pk & 0xffffffffu) * (1.f / 16777216.f) + 1.0f;
        g_dis[i]   = rsqrtf(d);
        g_selfw[i] = 1.0f / d;
        atomicAdd(&sh[v < 255 ? v : 255], 1);
    }
    __syncthreads();
    if (sh[tid]) atomicAdd(&g_dhist[tid], sh[tid]);
}

// scan dhist -> doff (1 block, 256 threads)
__global__ void k_scanh() {
    __shared__ int s[256];
    int t = threadIdx.x;
    int v = g_dhist[t];
    s[t] = v;
    __syncthreads();
    for (int off = 1; off < 256; off <<= 1) {
        int x = (t >= off) ? s[t - off] : 0;
        __syncthreads();
        s[t] += x;
        __syncthreads();
    }
    g_doff[t] = s[t] - v;        // exclusive bucket offsets
}

// counting-sort nodes by degree; record node->pos and sorted metadata
__global__ void k_sort() {
    __shared__ int sh[256];
    __shared__ int base[256];
    int tid = threadIdx.x;
    if (tid < 256) sh[tid] = 0;
    __syncthreads();
    int i = blockIdx.x * 1024 + tid;
    bool act = (i < NN);
    int c = 0, d = 0, inblk = 0;
    if (act) {
        c = (int)(g_pk[i] >> 32);
        d = c < 255 ? c : 255;
        inblk = atomicAdd(&sh[d], 1);
    }
    __syncthreads();
    if (tid < 256) base[tid] = sh[tid] ? atomicAdd(&g_doff[tid], sh[tid]) : 0;
    __syncthreads();
    if (act) {
        int pos = base[d] + inblk;
        g_snode[pos]  = make_int2(i, __float_as_int(g_selfw[i]));
        g_sdeg[pos]   = c;
        g_sortpos[i]  = pos;
    }
}

// per-group (8 nodes) max degree
__global__ void k_gmax() {
    int g = blockIdx.x * blockDim.x + threadIdx.x;
    if (g >= NGRP) return;
    int m = 0;
    #pragma unroll
    for (int j = 0; j < 8; j++) {
        int pos = g * 8 + j;
        if (pos < NN) { int c = g_sdeg[pos]; m = c > m ? c : m; }
    }
    g_gdeg[g] = m;
}

// scan group slot sizes -> g_goff (1 block, 1024 threads, chunked with carry)
__global__ void k_gscan() {
    __shared__ int s[1024];
    __shared__ int carry;
    int tid = threadIdx.x;
    if (tid == 0) { carry = 0; g_goff[0] = 0; }
    __syncthreads();
    for (int c0 = 0; c0 < NGRP; c0 += 1024) {
        int g = c0 + tid;
        int v = (g < NGRP) ? 8 * g_gdeg[g] : 0;
        s[tid] = v;
        __syncthreads();
        for (int off = 1; off < 1024; off <<= 1) {
            int x = (tid >= off) ? s[tid - off] : 0;
            __syncthreads();
            s[tid] += x;
            __syncthreads();
        }
        if (g < NGRP) g_goff[g + 1] = carry + s[tid];
        __syncthreads();
        if (tid == 1023) carry += s[1023];
        __syncthreads();
    }
}

// fill padding slots with {src=0, norm=0}
__global__ void k_pad() {
    int pos = blockIdx.x * blockDim.x + threadIdx.x;
    if (pos >= NN) return;
    int g = pos >> 3, lane = pos & 7;
    int c = g_sdeg[pos];
    int base = g_goff[g];
    int K = (g_goff[g + 1] - base) >> 3;
    for (int k = c; k < K; k++)
        g_edge2[base + k * 8 + lane] = make_float2(__int_as_float(0), 0.f);
}

// scatter edges into the transposed layout
__global__ void k_scatter(const void* ei, const float* __restrict__ w) {
    bool is64 = (g_is64 != 0);
    for (int e = blockIdx.x * blockDim.x + threadIdx.x; e < EE;
         e += gridDim.x * blockDim.x) {
        int r = eidx(ei, is64, e);
        int c = eidx(ei, is64, (long long)EE + e);
        int k    = atomicAdd(&g_cnt[c], 1);
        int sp   = g_sortpos[c];
        int slot = g_goff[sp >> 3] + k * 8 + (sp & 7);
        g_edge2[slot] = make_float2(__int_as_float(r), g_dis[r] * w[e] * g_dis[c]);
    }
}

// ---------------- layer 0 GEMM: x[N,128] @ W0[128,16] -> g_hb0 (fp16) -------
__global__ void k_gemm0(const float* __restrict__ x, const float* __restrict__ W0) {
    __shared__ float Ws[DIN * HID];   // 8 KB
    __shared__ float xs[16 * DIN];    // 8 KB
    int tid = threadIdx.x;
    for (int i = tid; i < DIN * HID; i += 256) Ws[i] = W0[i];
    int n0 = blockIdx.x * 16;
    for (int i = tid; i < 16 * DIN; i += 256) {
        int nn = n0 + i / DIN;
        xs[i] = (nn < NN) ? x[(size_t)nn * DIN + (i % DIN)] : 0.f;
    }
    __syncthreads();
    int ln = tid >> 4, f = tid & 15;
    int n = n0 + ln;
    if (n < NN) {
        float acc = 0.f;
        #pragma unroll
        for (int k = 0; k < DIN; k++) acc += xs[ln * DIN + k] * Ws[k * HID + f];
        reinterpret_cast<__half*>(g_hb0)[n * HID + f] = __float2half_rn(acc);
    }
}

// ---------------- agg mainloop core (shared by fused + last) ----------------
// 4 lanes per node (lane owns 4 feats as uint2 of halves); 8 nodes per warp.
// Unroll 8 with software-pipelined meta prefetch: 8 feature LDGs stay in
// flight per warp while the previous batch's FMAs retire.
__device__ __forceinline__ void agg_core(const uint2* __restrict__ tq,
                                         const float2* __restrict__ ep,
                                         int K, int l4, float* acc) {
    int k = 0;
    if (K >= 8) {
        float2 e[8];
        #pragma unroll
        for (int j = 0; j < 8; j++) e[j] = ep[j * 8];
        for (; k + 16 <= K; k += 8) {
            uint2 v[8];
            float w8[8];
            #pragma unroll
            for (int j = 0; j < 8; j++) {
                v[j]  = tq[__float_as_int(e[j].x) * 4 + l4];
                w8[j] = e[j].y;
            }
            #pragma unroll
            for (int j = 0; j < 8; j++) e[j] = ep[(k + 8 + j) * 8];  // prefetch
            #pragma unroll
            for (int j = 0; j < 8; j++) {
                float f[4];
                cvt4(v[j], f);
                acc[0] += w8[j] * f[0]; acc[1] += w8[j] * f[1];
                acc[2] += w8[j] * f[2]; acc[3] += w8[j] * f[3];
            }
        }
        // last full batch (edges k..k+7 already in e)
        {
            uint2 v[8];
            float w8[8];
            #pragma unroll
            for (int j = 0; j < 8; j++) {
                v[j]  = tq[__float_as_int(e[j].x) * 4 + l4];
                w8[j] = e[j].y;
            }
            #pragma unroll
            for (int j = 0; j < 8; j++) {
                float f[4];
                cvt4(v[j], f);
                acc[0] += w8[j] * f[0]; acc[1] += w8[j] * f[1];
                acc[2] += w8[j] * f[2]; acc[3] += w8[j] * f[3];
            }
            k += 8;
        }
    }
    for (; k < K; k++) {
        float2 ed = ep[k * 8];
        float f[4];
        cvt4(tq[__float_as_int(ed.x) * 4 + l4], f);
        acc[0] += ed.y * f[0]; acc[1] += ed.y * f[1];
        acc[2] += ed.y * f[2]; acc[3] += ed.y * f[3];
    }
}

// ---------------- fused agg(+bias+relu) + next-layer GEMM -------------------
template <int FOUT>
__global__ void __launch_bounds__(256) k_fused(const float* __restrict__ bias,
                                               const float* __restrict__ Wn, int rb) {
    __shared__ float Ws[HID * 16];
    int tid = threadIdx.x;
    for (int i = tid; i < HID * 16; i += 256) {
        int k = i >> 4, fo = i & 15;
        Ws[i] = (fo < FOUT) ? Wn[k * FOUT + fo] : 0.f;
    }
    __syncthreads();

    int g = (blockIdx.x * 256 + tid) >> 5;        // group = warp (8 nodes)
    if (g >= NGRP) g = NGRP - 1;                  // dup warps redo last group
    int lane = tid & 31;
    int p  = lane >> 2;
    int l4 = lane & 3;

    int2  sn = g_snode[g * 8 + p];
    int   n  = sn.x;
    float sw = __int_as_float(sn.y);
    int base = g_goff[g];
    int K    = (g_goff[g + 1] - base) >> 3;       // padded edges per member

    const uint2* __restrict__ tq  = rb ? g_hb1 : g_hb0;
    uint2*       __restrict__ dst = rb ? g_hb0 : g_hb1;

    float acc[4], f0[4];
    cvt4(tq[n * 4 + l4], f0);
    #pragma unroll
    for (int j = 0; j < 4; j++) acc[j] = sw * f0[j];

    agg_core(tq, g_edge2 + base + p, K, l4, acc);

    // bias + relu (agg feat dim is 16 on all fused layers)
    float4 bv = *(const float4*)(bias + l4 * 4);
    float h[4];
    h[0] = fmaxf(acc[0] + bv.x, 0.f);
    h[1] = fmaxf(acc[1] + bv.y, 0.f);
    h[2] = fmaxf(acc[2] + bv.z, 0.f);
    h[3] = fmaxf(acc[3] + bv.w, 0.f);

    // reconstruct full 16-feat row within the 4-lane group (width-4 shuffles)
    float hrow[16];
    #pragma unroll
    for (int q = 0; q < 16; q++)
        hrow[q] = __shfl_sync(0xffffffffu, h[q & 3], q >> 2, 4);

    // next-layer GEMM: this lane produces output feats l4*4 .. l4*4+3
    float o[4] = {0, 0, 0, 0};
    #pragma unroll
    for (int kk = 0; kk < HID; kk++) {
        float hk = hrow[kk];
        const float* wr = &Ws[kk * 16 + l4 * 4];
        o[0] += hk * wr[0]; o[1] += hk * wr[1];
        o[2] += hk * wr[2]; o[3] += hk * wr[3];
    }
    dst[n * 4 + l4] = pack4(o);   // dup warps write identical data
}

// ---------------- final aggregation (F=12) into harness out (fp32) ----------
// tmp rows are stride-16 halves (cols 12..15 zero-padded by k_fused<12>).
__global__ void __launch_bounds__(256) k_agg_last(const float* __restrict__ bias,
                                                  float* __restrict__ outp) {
    int g = (blockIdx.x * 256 + threadIdx.x) >> 5;
    if (g >= NGRP) g = NGRP - 1;
    int lane = threadIdx.x & 31;
    int p  = lane >> 2;
    int l4 = lane & 3;

    int2  sn = g_snode[g * 8 + p];
    int   n  = sn.x;
    float sw = __int_as_float(sn.y);
    int base = g_goff[g];
    int K    = (g_goff[g + 1] - base) >> 3;

    const uint2* __restrict__ tq = g_hb0;   // 12 fused layers end in hb0

    float acc[4], f0[4];
    cvt4(tq[n * 4 + l4], f0);
    #pragma unroll
    for (int j = 0; j < 4; j++) acc[j] = sw * f0[j];

    agg_core(tq, g_edge2 + base + p, K, l4, acc);

    if (l4 < 3) {   // only feats 0..11 exist; rows are 48B (16B-aligned)
        float4 bv = *(const float4*)(bias + l4 * 4);
        float4 r;
        r.x = fmaxf(acc[0] + bv.x, 0.f);
        r.y = fmaxf(acc[1] + bv.y, 0.f);
        r.z = fmaxf(acc[2] + bv.z, 0.f);
        r.w = fmaxf(acc[3] + bv.w, 0.f);
        *(float4*)(outp + (size_t)n * DOUT + l4 * 4) = r;
    }
}

// ---------------- launch ----------------------------------------------------
extern "C" void kernel_launch(void* const* d_in, const int* in_sizes, int n_in,
                              void* d_out, int out_size) {
    const float* x     = (const float*)d_in[0];
    const void*  ei    = d_in[1];
    const float* w     = (const float*)d_in[2];
    const float* W0    = (const float*)d_in[3];
    const float* b0    = (const float*)d_in[4];
    const float* Wmid  = (const float*)d_in[5];
    const float* bmid  = (const float*)d_in[6];
    const float* Wlast = (const float*)d_in[7];
    const float* blast = (const float*)d_in[8];
    float* out = (float*)d_out;

    const int TB = 256;
    const int nblkN = (NN + TB - 1) / TB;
    const int nblkE = 2048;
    const int nblkW = (NGRP * 32 + TB - 1) / TB;   // 1 warp per 8-node group

    // --- preprocessing ---
    k_init<<<nblkN, TB>>>((const unsigned int*)ei);
    k_degcnt<<<nblkE, TB>>>(ei, w);
    k_normhist<<<nblkN, TB>>>();
    k_scanh<<<1, 256>>>();
    k_sort<<<(NN + 1023) / 1024, 1024>>>();
    k_gmax<<<(NGRP + TB - 1) / TB, TB>>>();
    k_gscan<<<1, 1024>>>();
    k_pad<<<nblkN, TB>>>();
    k_scatter<<<nblkE, TB>>>(ei, w);

    // --- layer 0 GEMM -> hb0 (fp16) ---
    k_gemm0<<<(NN + 15) / 16, 256>>>(x, W0);

    // --- 12 fused agg+gemm layers (ping-pong hb0 <-> hb1) ---
    k_fused<HID><<<nblkW, TB>>>(b0, Wmid, 0);                        // l=0
    for (int l = 1; l <= 10; l++) {
        k_fused<HID><<<nblkW, TB>>>(bmid + (size_t)(l - 1) * HID,
                                    Wmid + (size_t)l * HID * HID, l & 1);
    }
    k_fused<DOUT><<<nblkW, TB>>>(bmid + (size_t)10 * HID, Wlast, 1); // l=11 -> hb0

    // --- final aggregation (conv 12) straight into d_out (fp32) ---
    k_agg_last<<<nblkW, TB>>>(blast, out);
}